// round 5
// baseline (speedup 1.0000x reference)
#include <cuda_runtime.h>
#include <cuda_fp16.h>
#include <math.h>
#include <stdint.h>

// ---------------------------------------------------------------------------
// Problem constants
// ---------------------------------------------------------------------------
#define NB   64     // batch
#define CCH  64     // channels
#define TT   300    // time
#define VV   25     // vertices
#define SS   3      // subsets
#define IC   16     // inter channels
#define TV   (TT*VV)          // 7500
#define KROWS (IC*TT)         // 4800

// Scratch (device globals — no allocation allowed)
__device__ __half g_t1h[SS * NB * IC * TV];   // fp16 scratch (att-only path)
__device__ __half g_t2h[SS * NB * IC * TV];
__device__ float  g_A1[SS * NB * VV * VV];
__device__ float  g_Afull[SS * VV * VV];

// ---------------------------------------------------------------------------
// Packed fp32x2 helpers (used in k_aggz)
// ---------------------------------------------------------------------------
__device__ __forceinline__ void fma2(uint64_t& d, uint64_t a, uint64_t b) {
    asm("fma.rn.f32x2 %0, %1, %2, %0;" : "+l"(d) : "l"(a), "l"(b));
}
__device__ __forceinline__ uint64_t pack2(float lo, float hi) {
    uint64_t r;
    asm("mov.b64 %0, {%1, %2};" : "=l"(r) : "f"(lo), "f"(hi));
    return r;
}
__device__ __forceinline__ float2 unpack2(uint64_t v) {
    float2 r;
    asm("mov.b64 {%0, %1}, %2;" : "=f"(r.x), "=f"(r.y) : "l"(v));
    return r;
}

// ---------------------------------------------------------------------------
// K0: A_full = A + PA + (8A^4 - 4A^2 - 4A + I)
// ---------------------------------------------------------------------------
__global__ void k_afull(const float* __restrict__ A, const float* __restrict__ PA) {
    for (int idx = threadIdx.x; idx < SS * VV * VV; idx += blockDim.x) {
        int r = idx % (VV * VV);
        int v1 = r / VV, v2 = r % VV;
        float a = A[idx];
        float a2 = a * a;
        float ch = 8.f * a2 * a2 - 4.f * a2 - 4.f * a + (v1 == v2 ? 1.f : 0.f);
        g_Afull[idx] = a + PA[idx] + ch;
    }
}

// ---------------------------------------------------------------------------
// K1: t1/t2 = slim_conv(x, WT1/WT2, pad_t=4), fp16 HFMA2 inner loops.
//   2x fp32 FLOP rate.  fp16 accumulation in 8-ci chunks, fp32 spill.
// grid: (10, N, S), block: 416 (400 active = 16 t-pairs x 25 v)
// smem: W1,W2 as half [ci][dt][co16], uint4-loadable.  36864 B.
// ---------------------------------------------------------------------------
__global__ __launch_bounds__(416, 1)
void k_conv(const float* __restrict__ x,
            const float* __restrict__ WT1, const float* __restrict__ bT1,
            const float* __restrict__ WT2, const float* __restrict__ bT2,
            const float* __restrict__ weights) {
    const int s = blockIdx.z;
    const int n = blockIdx.y;
    extern __shared__ __half swh[];
    __half* sW1 = swh;             // IC*CCH*9 = 9216 halfs
    __half* sW2 = swh + 9216;      // 9216 halfs

    const float* W1g = WT1 + s * IC * CCH * 9;
    const float* W2g = WT2 + s * IC * CCH * 9;
    for (int idx = threadIdx.x; idx < IC * CCH * 9; idx += 416) {
        int ci = idx / 144;
        int r = idx - ci * 144;
        int dt = r >> 4;
        int co = r & 15;
        int gidx = (co * CCH + ci) * 9 + dt;
        sW1[idx] = __float2half(W1g[gidx]);
        sW2[idx] = __float2half(W2g[gidx]);
    }
    __syncthreads();

    const int tid = threadIdx.x;
    if (tid >= 400) return;
    const int tp = tid / 25;
    const int v = tid - tp * 25;
    const int t0 = blockIdx.x * 32 + tp * 2;
    if (t0 >= TT) return;

    // fp32 master accumulators: 8 co-pairs x {t0,t1} x {conv1,conv2}
    float2 A10[8], A11[8], A20[8], A21[8];
#pragma unroll
    for (int i = 0; i < 8; i++) {
        A10[i] = make_float2(0.f, 0.f); A11[i] = make_float2(0.f, 0.f);
        A20[i] = make_float2(0.f, 0.f); A21[i] = make_float2(0.f, 0.f);
    }

    const uint4* w1q = (const uint4*)sW1;   // (ci*9+dt)*2 + {0,1}: 8 co each
    const uint4* w2q = (const uint4*)sW2;
    const float* xb = x + n * CCH * TV + v;

    for (int cib = 0; cib < CCH; cib += 8) {
        // fp16 chunk accumulators
        half2 h10[8], h11[8], h20[8], h21[8];
        const half2 hz = __float2half2_rn(0.f);
#pragma unroll
        for (int i = 0; i < 8; i++) { h10[i] = hz; h11[i] = hz; h20[i] = hz; h21[i] = hz; }

#pragma unroll
        for (int cc = 0; cc < 8; cc++) {
            const int ci = cib + cc;
            const float* xp = xb + ci * TV;
            half2 xh[10];
#pragma unroll
            for (int k = 0; k < 10; k++) {
                int tt = t0 - 4 + k;
                float xv = (tt >= 0 && tt < TT) ? __ldg(xp + tt * VV) : 0.f;
                xh[k] = __float2half2_rn(xv);
            }
#pragma unroll
            for (int dt = 0; dt < 9; dt++) {
                uint4 wa = w1q[(ci * 9 + dt) * 2];
                uint4 wb = w1q[(ci * 9 + dt) * 2 + 1];
                uint4 wc = w2q[(ci * 9 + dt) * 2];
                uint4 wd = w2q[(ci * 9 + dt) * 2 + 1];
                half2 w1h[8], w2h[8];
                *(uint4*)(w1h) = wa; *(uint4*)(w1h + 4) = wb;
                *(uint4*)(w2h) = wc; *(uint4*)(w2h + 4) = wd;
                half2 x0 = xh[dt], x1 = xh[dt + 1];
#pragma unroll
                for (int p = 0; p < 8; p++) {
                    h10[p] = __hfma2(w1h[p], x0, h10[p]);
                    h11[p] = __hfma2(w1h[p], x1, h11[p]);
                    h20[p] = __hfma2(w2h[p], x0, h20[p]);
                    h21[p] = __hfma2(w2h[p], x1, h21[p]);
                }
            }
        }
        // spill chunk into fp32
#pragma unroll
        for (int p = 0; p < 8; p++) {
            float2 f;
            f = __half22float2(h10[p]); A10[p].x += f.x; A10[p].y += f.y;
            f = __half22float2(h11[p]); A11[p].x += f.x; A11[p].y += f.y;
            f = __half22float2(h20[p]); A20[p].x += f.x; A20[p].y += f.y;
            f = __half22float2(h21[p]); A21[p].x += f.x; A21[p].y += f.y;
        }
    }

    const float ws1 = __ldg(weights + 1), ws2 = __ldg(weights + 2);
    const float ws3 = __ldg(weights + 3), ws4 = __ldg(weights + 4);
    const int base = ((s * NB + n) * IC) * TV + t0 * VV + v;
#pragma unroll
    for (int co = 0; co < IC; co++) {
        // slim splits for out_c=16: 9, 11, 12, 14
        float sc = (co < 9) ? 1.f : (co < 11) ? ws1 : (co < 12) ? ws2 : (co < 14) ? ws3 : ws4;
        float b1 = __ldg(bT1 + s * IC + co);
        float b2 = __ldg(bT2 + s * IC + co);
        int o = base + co * TV;
        int p = co >> 1;
        float v10 = (co & 1) ? A10[p].y : A10[p].x;
        float v11 = (co & 1) ? A11[p].y : A11[p].x;
        float v20 = (co & 1) ? A20[p].y : A20[p].x;
        float v21 = (co & 1) ? A21[p].y : A21[p].x;
        g_t1h[o]      = __float2half(sc * (v10 + b1));
        g_t1h[o + VV] = __float2half(sc * (v11 + b1));
        g_t2h[o]      = __float2half(sc * (v20 + b2));
        g_t2h[o + VV] = __float2half(sc * (v21 + b2));
    }
}

// ---------------------------------------------------------------------------
// K2: attention logits + softmax(axis=-2 over v1) + A_full -> A1
//   reads fp16 t1/t2, fp32 math.
// ---------------------------------------------------------------------------
__global__ __launch_bounds__(640, 2)
void k_att() {
    const int n = blockIdx.x;
    const int s = blockIdx.y;
    __shared__ float s1[64 * VV];
    __shared__ float s2[64 * VV];
    __shared__ float sl[VV * VV];

    const __half* t1b = g_t1h + (size_t)(s * NB + n) * IC * TV;
    const __half* t2b = g_t2h + (size_t)(s * NB + n) * IC * TV;

    const int tid = threadIdx.x;
    const int v1 = tid / 25;
    const int v2 = tid - v1 * 25;
    const bool act = tid < VV * VV;
    float acc = 0.f;

    for (int ch = 0; ch < KROWS / 64; ch++) {
        for (int idx = tid; idx < 64 * VV; idx += 640) {
            int row = idx / VV, vv = idx - row * VV;
            int cr = ch * 64 + row;
            int c = cr / TT, t = cr - c * TT;
            int off = c * TV + t * VV + vv;
            s1[idx] = __half2float(t1b[off]);
            s2[idx] = __half2float(t2b[off]);
        }
        __syncthreads();
        if (act) {
#pragma unroll 8
            for (int k = 0; k < 64; k++)
                acc += s1[k * VV + v1] * s2[k * VV + v2];
        }
        __syncthreads();
    }

    if (act) sl[tid] = acc * (1.0f / (float)KROWS);
    __syncthreads();

    if (tid < VV) {
        const int c2 = tid;
        float m = -1e30f;
#pragma unroll
        for (int r = 0; r < VV; r++) m = fmaxf(m, sl[r * VV + c2]);
        float sum = 0.f;
#pragma unroll
        for (int r = 0; r < VV; r++) sum += expf(sl[r * VV + c2] - m);
        float inv = 1.f / sum;
        const float* af = g_Afull + s * VV * VV;
        float* a1o = g_A1 + (size_t)(s * NB + n) * VV * VV;
#pragma unroll
        for (int r = 0; r < VV; r++)
            a1o[r * VV + c2] = af[r * VV + c2] + expf(sl[r * VV + c2] - m) * inv;
    }
}

// ---------------------------------------------------------------------------
// K3: agg + Wd fold + BN + residual + relu, f32x2 inner loops (unchanged).
// ---------------------------------------------------------------------------
#define TT2 10
__global__ __launch_bounds__(256, 2)
void k_aggz(const float* __restrict__ x,
            const float* __restrict__ Wd, const float* __restrict__ bd,
            const float* __restrict__ weights,
            const float* __restrict__ bng, const float* __restrict__ bnb,
            const float* __restrict__ bnm, const float* __restrict__ bnv,
            float* __restrict__ out) {
    extern __shared__ float sm[];
    float* xs  = sm;              // 250*68 = 17000
    float* WdT = xs + 17000;      // 4096
    float* A1s = WdT + 4096;      // 625
    float* ka  = A1s + 625;       // 64
    float* kb  = ka + 64;         // 64

    const int n  = blockIdx.y;
    const int t0 = blockIdx.x * TT2;
    const int tid = threadIdx.x;
    const int nb = n * CCH * TV;

    for (int idx = tid; idx < CCH * TT2 * VV; idx += 256) {
        int ci = idx / (TT2 * VV);
        int tv = idx - ci * (TT2 * VV);
        xs[tv * 68 + ci] = x[nb + ci * TV + t0 * VV + tv];
    }
    if (tid < CCH) {
        int co = tid;
        float ws1 = weights[1], ws2 = weights[2], ws3 = weights[3], ws4 = weights[4];
        // slim splits for out_c=64: 38, 44, 51, 57
        float sc = (co < 38) ? 1.f : (co < 44) ? ws1 : (co < 51) ? ws2 : (co < 57) ? ws3 : ws4;
        float bdsum = bd[co] + bd[CCH + co] + bd[2 * CCH + co];
        float fa = bng[co] * rsqrtf(bnv[co] + 1e-5f);
        ka[co] = fa * sc;
        kb[co] = fa * sc * bdsum + bnb[co] - bnm[co] * fa;
    }

    uint64_t zacc[32];
    const uint64_t z2 = pack2(0.f, 0.f);
#pragma unroll
    for (int i = 0; i < 32; i++) zacc[i] = z2;

    const int tv = tid;
    const bool act = tid < TT2 * VV;
    const int tloc = tv / 25;
    const int v2 = tv - tloc * 25;

    for (int s = 0; s < SS; s++) {
        __syncthreads();
        for (int idx = tid; idx < CCH * CCH; idx += 256) {
            int ci = idx >> 6;
            int co = idx & 63;
            WdT[ci * 64 + co] = Wd[(s * CCH + co) * CCH + ci];
        }
        for (int idx = tid; idx < VV * VV; idx += 256)
            A1s[idx] = g_A1[(size_t)(s * NB + n) * VV * VV + idx];
        __syncthreads();

        if (act) {
#pragma unroll
            for (int cb = 0; cb < 64; cb += 16) {
                uint64_t ap[8];
#pragma unroll
                for (int i = 0; i < 8; i++) ap[i] = z2;
#pragma unroll
                for (int vv1 = 0; vv1 < VV; vv1++) {
                    float aw = A1s[vv1 * VV + v2];
                    uint64_t awp = pack2(aw, aw);
                    const ulonglong2* xp = (const ulonglong2*)(xs + (tloc * 25 + vv1) * 68 + cb);
#pragma unroll
                    for (int q = 0; q < 4; q++) {
                        ulonglong2 xv = xp[q];
                        fma2(ap[2*q],   xv.x, awp);
                        fma2(ap[2*q+1], xv.y, awp);
                    }
                }
#pragma unroll
                for (int i = 0; i < 8; i++) {
                    float2 af = unpack2(ap[i]);
                    uint64_t av0 = pack2(af.x, af.x);
                    uint64_t av1 = pack2(af.y, af.y);
                    const ulonglong2* w0 = (const ulonglong2*)(WdT + (cb + 2*i) * 64);
                    const ulonglong2* w1 = (const ulonglong2*)(WdT + (cb + 2*i + 1) * 64);
#pragma unroll
                    for (int q = 0; q < 16; q++) {
                        ulonglong2 wv0 = w0[q];
                        fma2(zacc[2*q],   wv0.x, av0);
                        fma2(zacc[2*q+1], wv0.y, av0);
                    }
#pragma unroll
                    for (int q = 0; q < 16; q++) {
                        ulonglong2 wv1 = w1[q];
                        fma2(zacc[2*q],   wv1.x, av1);
                        fma2(zacc[2*q+1], wv1.y, av1);
                    }
                }
            }
        }
    }

    if (act) {
        const float* xrow = xs + (tloc * 25 + v2) * 68;
        const int ob = nb + t0 * VV + tv;
#pragma unroll
        for (int cp = 0; cp < 32; cp++) {
            float2 zz = unpack2(zacc[cp]);
            int c0 = 2 * cp, c1 = 2 * cp + 1;
            float val0 = ka[c0] * zz.x + kb[c0] + xrow[c0];
            float val1 = ka[c1] * zz.y + kb[c1] + xrow[c1];
            out[ob + c0 * TV] = fmaxf(val0, 0.f);
            out[ob + c1 * TV] = fmaxf(val1, 0.f);
        }
    }
}

// ---------------------------------------------------------------------------
// launch
// ---------------------------------------------------------------------------
extern "C" void kernel_launch(void* const* d_in, const int* in_sizes, int n_in,
                              void* d_out, int out_size) {
    const float* x    = (const float*)d_in[0];
    const float* wts  = (const float*)d_in[1];
    const float* A    = (const float*)d_in[2];
    const float* PA   = (const float*)d_in[3];
    const float* Wd   = (const float*)d_in[4];
    const float* bd   = (const float*)d_in[5];
    const float* WT1  = (const float*)d_in[6];
    const float* bT1  = (const float*)d_in[7];
    const float* WT2  = (const float*)d_in[8];
    const float* bT2  = (const float*)d_in[9];
    const float* bng  = (const float*)d_in[10];
    const float* bnb  = (const float*)d_in[11];
    const float* bnm  = (const float*)d_in[12];
    const float* bnv  = (const float*)d_in[13];
    float* out = (float*)d_out;

    const int conv_smem = 2 * IC * CCH * 9 * 2;           // 36864 (fp16)
    const int aggz_smem = (17000 + 4096 + 625 + 128) * 4; // 87396
    cudaFuncSetAttribute(k_conv, cudaFuncAttributeMaxDynamicSharedMemorySize, conv_smem);
    cudaFuncSetAttribute(k_aggz, cudaFuncAttributeMaxDynamicSharedMemorySize, aggz_smem);

    k_afull<<<1, 640>>>(A, PA);
    k_conv<<<dim3(10, NB, SS), 416, conv_smem>>>(x, WT1, bT1, WT2, bT2, wts);
    k_att<<<dim3(NB, SS), 640>>>();
    k_aggz<<<dim3(TT / TT2, NB), 256, aggz_smem>>>(x, Wd, bd, wts, bng, bnb, bnm, bnv, out);
}

// round 6
// speedup vs baseline: 1.0424x; 1.0424x over previous
#include <cuda_runtime.h>
#include <cuda_fp16.h>
#include <math.h>
#include <stdint.h>

// ---------------------------------------------------------------------------
// Problem constants
// ---------------------------------------------------------------------------
#define NB   64     // batch
#define CCH  64     // channels
#define TT   300    // time
#define VV   25     // vertices
#define SS   3      // subsets
#define IC   16     // inter channels
#define TV   (TT*VV)          // 7500
#define KROWS (IC*TT)         // 4800

// Scratch (device globals — no allocation allowed)
__device__ __half g_t1h[SS * NB * IC * TV];
__device__ __half g_t2h[SS * NB * IC * TV];
__device__ float  g_A1[SS * NB * VV * VV];
__device__ float  g_Afull[SS * VV * VV];

// ---------------------------------------------------------------------------
// Packed fp32x2 helpers (SASS FFMA2)
// ---------------------------------------------------------------------------
__device__ __forceinline__ void fma2(uint64_t& d, uint64_t a, uint64_t b) {
    asm("fma.rn.f32x2 %0, %1, %2, %0;" : "+l"(d) : "l"(a), "l"(b));
}
__device__ __forceinline__ uint64_t pack2(float lo, float hi) {
    uint64_t r;
    asm("mov.b64 %0, {%1, %2};" : "=l"(r) : "f"(lo), "f"(hi));
    return r;
}
__device__ __forceinline__ float2 unpack2(uint64_t v) {
    float2 r;
    asm("mov.b64 {%0, %1}, %2;" : "=f"(r.x), "=f"(r.y) : "l"(v));
    return r;
}

// ---------------------------------------------------------------------------
// K0: A_full = A + PA + (8A^4 - 4A^2 - 4A + I)
// ---------------------------------------------------------------------------
__global__ void k_afull(const float* __restrict__ A, const float* __restrict__ PA) {
    for (int idx = threadIdx.x; idx < SS * VV * VV; idx += blockDim.x) {
        int r = idx % (VV * VV);
        int v1 = r / VV, v2 = r % VV;
        float a = A[idx];
        float a2 = a * a;
        float ch = 8.f * a2 * a2 - 4.f * a2 - 4.f * a + (v1 == v2 ? 1.f : 0.f);
        g_Afull[idx] = a + PA[idx] + ch;
    }
}

// ---------------------------------------------------------------------------
// K1 v3: slim_conv with high t-reuse.
//   Thread = (cog, tg, v): computes 8 co-slots x 10 t-points x 1 v.
//   cog 0..3: {conv1 co0-7, conv1 co8-15, conv2 co0-7, conv2 co8-15}.
//   Weight LDS traffic /5 vs old (10 t per weight read).
// grid: (6, N, S); block 500; smem: W [ci][dt][32 slots] float = 73728 B
// ---------------------------------------------------------------------------
__global__ __launch_bounds__(500, 1)
void k_conv(const float* __restrict__ x,
            const float* __restrict__ WT1, const float* __restrict__ bT1,
            const float* __restrict__ WT2, const float* __restrict__ bT2,
            const float* __restrict__ weights) {
    const int s = blockIdx.z;
    const int n = blockIdx.y;
    extern __shared__ float sW[];   // (ci*9+dt)*32 + cv*16 + co

    const float* W1g = WT1 + s * IC * CCH * 9;
    const float* W2g = WT2 + s * IC * CCH * 9;
    for (int idx = threadIdx.x; idx < CCH * 9 * 32; idx += 500) {
        int ci  = idx / 288;
        int rr  = idx - ci * 288;
        int dt  = rr >> 5;
        int slot = rr & 31;
        int cv  = slot >> 4;
        int co  = slot & 15;
        const float* Wg = cv ? W2g : W1g;
        sW[idx] = Wg[(co * CCH + ci) * 9 + dt];
    }
    __syncthreads();

    const int tid = threadIdx.x;
    const int cog = tid / 125;           // 0..3
    const int r   = tid - cog * 125;
    const int tg  = r / 25;              // 0..4
    const int v   = r - tg * 25;
    const int t0  = blockIdx.x * 50 + tg * 10;
    const int cv  = cog >> 1;
    const int cb  = (cog & 1) * 8;

    // acc[p*10 + t]: p = co-pair within the 8 slots, t = 0..9
    uint64_t acc[40];
    const uint64_t z2 = pack2(0.f, 0.f);
#pragma unroll
    for (int i = 0; i < 40; i++) acc[i] = z2;

    const float* xb = x + n * CCH * TV + v;
    const float* wbase = sW + cog * 8;

    for (int ci = 0; ci < CCH; ci++) {
        const float* xp = xb + ci * TV;
        float xr[18];
#pragma unroll
        for (int k = 0; k < 18; k++) {
            int tt = t0 - 4 + k;
            xr[k] = (tt >= 0 && tt < TT) ? __ldg(xp + tt * VV) : 0.f;
        }
#pragma unroll
        for (int dt = 0; dt < 9; dt++) {
            const ulonglong2* wp = (const ulonglong2*)(wbase + (ci * 9 + dt) * 32);
            ulonglong2 wA = wp[0];
            ulonglong2 wB = wp[1];
#pragma unroll
            for (int t = 0; t < 10; t++) {
                uint64_t xd = pack2(xr[dt + t], xr[dt + t]);
                fma2(acc[t],      wA.x, xd);
                fma2(acc[10 + t], wA.y, xd);
                fma2(acc[20 + t], wB.x, xd);
                fma2(acc[30 + t], wB.y, xd);
            }
        }
    }

    const float ws1 = __ldg(weights + 1), ws2 = __ldg(weights + 2);
    const float ws3 = __ldg(weights + 3), ws4 = __ldg(weights + 4);
    const float* bsrc = cv ? bT2 : bT1;
    __half* gout = cv ? g_t2h : g_t1h;
    const size_t obase = (size_t)(s * NB + n) * IC * TV + v;
#pragma unroll
    for (int j = 0; j < 8; j++) {
        int co = cb + j;
        // slim splits for out_c=16: 9, 11, 12, 14
        float sc = (co < 9) ? 1.f : (co < 11) ? ws1 : (co < 12) ? ws2 : (co < 14) ? ws3 : ws4;
        float b = __ldg(bsrc + s * IC + co);
        size_t oc = obase + (size_t)co * TV + (size_t)t0 * VV;
#pragma unroll
        for (int t = 0; t < 10; t++) {
            float2 f = unpack2(acc[(j >> 1) * 10 + t]);
            float val = (j & 1) ? f.y : f.x;
            gout[oc + t * VV] = __float2half(sc * (val + b));
        }
    }
}

// ---------------------------------------------------------------------------
// K2: attention logits + softmax(axis=-2 over v1) + A_full -> A1 (fp16 in)
// ---------------------------------------------------------------------------
__global__ __launch_bounds__(640, 2)
void k_att() {
    const int n = blockIdx.x;
    const int s = blockIdx.y;
    __shared__ float s1[64 * VV];
    __shared__ float s2[64 * VV];
    __shared__ float sl[VV * VV];

    const __half* t1b = g_t1h + (size_t)(s * NB + n) * IC * TV;
    const __half* t2b = g_t2h + (size_t)(s * NB + n) * IC * TV;

    const int tid = threadIdx.x;
    const int v1 = tid / 25;
    const int v2 = tid - v1 * 25;
    const bool act = tid < VV * VV;
    float acc = 0.f;

    for (int ch = 0; ch < KROWS / 64; ch++) {
        for (int idx = tid; idx < 64 * VV; idx += 640) {
            int row = idx / VV, vv = idx - row * VV;
            int cr = ch * 64 + row;
            int c = cr / TT, t = cr - c * TT;
            int off = c * TV + t * VV + vv;
            s1[idx] = __half2float(t1b[off]);
            s2[idx] = __half2float(t2b[off]);
        }
        __syncthreads();
        if (act) {
#pragma unroll 8
            for (int k = 0; k < 64; k++)
                acc += s1[k * VV + v1] * s2[k * VV + v2];
        }
        __syncthreads();
    }

    if (act) sl[tid] = acc * (1.0f / (float)KROWS);
    __syncthreads();

    if (tid < VV) {
        const int c2 = tid;
        float m = -1e30f;
#pragma unroll
        for (int r = 0; r < VV; r++) m = fmaxf(m, sl[r * VV + c2]);
        float sum = 0.f;
#pragma unroll
        for (int r = 0; r < VV; r++) sum += expf(sl[r * VV + c2] - m);
        float inv = 1.f / sum;
        const float* af = g_Afull + s * VV * VV;
        float* a1o = g_A1 + (size_t)(s * NB + n) * VV * VV;
#pragma unroll
        for (int r = 0; r < VV; r++)
            a1o[r * VV + c2] = af[r * VV + c2] + expf(sl[r * VV + c2] - m) * inv;
    }
}

// ---------------------------------------------------------------------------
// K3 v2: two-phase agg + fold.
//   Phase a: thread=pt computes agg[64] (in 32-ci halves) -> sAgg smem.
//   Phase b: tiled GEMM z[250,64] += sAgg[250,64] x WdT[64,64];
//            thread = (ptg 0..31) x (cog 0..7): 8 pt x 8 co.
// grid (30, N), block 256.  smem ~155 KB.
// ---------------------------------------------------------------------------
#define TT2 10
__global__ __launch_bounds__(256, 1)
void k_aggz(const float* __restrict__ x,
            const float* __restrict__ Wd, const float* __restrict__ bd,
            const float* __restrict__ weights,
            const float* __restrict__ bng, const float* __restrict__ bnb,
            const float* __restrict__ bnm, const float* __restrict__ bnv,
            float* __restrict__ out) {
    extern __shared__ float sm[];
    float* xs   = sm;               // 250*68 = 17000
    float* WdT  = xs + 17000;       // 4096
    float* A1s  = WdT + 4096;       // 625
    float* ka   = A1s + 625;        // 64
    float* kb   = ka + 64;          // 64
    float* sAgg = kb + 64;          // 256*66 = 16896

    const int n  = blockIdx.y;
    const int t0 = blockIdx.x * TT2;
    const int tid = threadIdx.x;
    const int nb = n * CCH * TV;

    for (int idx = tid; idx < CCH * TT2 * VV; idx += 256) {
        int ci = idx / (TT2 * VV);
        int tv = idx - ci * (TT2 * VV);
        xs[tv * 68 + ci] = x[nb + ci * TV + t0 * VV + tv];
    }
    if (tid < CCH) {
        int co = tid;
        float ws1 = weights[1], ws2 = weights[2], ws3 = weights[3], ws4 = weights[4];
        // slim splits for out_c=64: 38, 44, 51, 57
        float sc = (co < 38) ? 1.f : (co < 44) ? ws1 : (co < 51) ? ws2 : (co < 57) ? ws3 : ws4;
        float bdsum = bd[co] + bd[CCH + co] + bd[2 * CCH + co];
        float fa = bng[co] * rsqrtf(bnv[co] + 1e-5f);
        ka[co] = fa * sc;
        kb[co] = fa * sc * bdsum + bnb[co] - bnm[co] * fa;
    }
    // zero pad rows of sAgg (pts 250..255) once
    if (tid >= 250) {
        for (int i = 0; i < 64; i++) sAgg[tid * 66 + i] = 0.f;
    }

    const int tv = tid;
    const bool act = tid < TT2 * VV;
    const int tloc = tv / 25;
    const int v2 = tv - tloc * 25;
    const int cog = tid & 7;     // phase-b co group
    const int ptg = tid >> 3;    // phase-b point group

    uint64_t zacc[32];
    const uint64_t z2 = pack2(0.f, 0.f);
#pragma unroll
    for (int i = 0; i < 32; i++) zacc[i] = z2;

    for (int s = 0; s < SS; s++) {
        __syncthreads();
        for (int idx = tid; idx < CCH * CCH; idx += 256) {
            int ci = idx >> 6;
            int co = idx & 63;
            WdT[ci * 64 + co] = Wd[(s * CCH + co) * CCH + ci];
        }
        for (int idx = tid; idx < VV * VV; idx += 256)
            A1s[idx] = g_A1[(size_t)(s * NB + n) * VV * VV + idx];
        __syncthreads();

        // phase a: agg for this thread's point, in 2 halves of 32 ci
        if (act) {
#pragma unroll
            for (int half = 0; half < 2; half++) {
                uint64_t ap[16];
#pragma unroll
                for (int i = 0; i < 16; i++) ap[i] = z2;
#pragma unroll
                for (int vv1 = 0; vv1 < VV; vv1++) {
                    float aw = A1s[vv1 * VV + v2];
                    uint64_t awp = pack2(aw, aw);
                    const ulonglong2* xp =
                        (const ulonglong2*)(xs + (tloc * 25 + vv1) * 68 + half * 32);
#pragma unroll
                    for (int q = 0; q < 8; q++) {
                        ulonglong2 xv = xp[q];
                        fma2(ap[2 * q],     xv.x, awp);
                        fma2(ap[2 * q + 1], xv.y, awp);
                    }
                }
                float* dst = sAgg + tv * 66 + half * 32;
#pragma unroll
                for (int i = 0; i < 16; i++) {
                    float2 f = unpack2(ap[i]);
                    dst[2 * i]     = f.x;
                    dst[2 * i + 1] = f.y;
                }
            }
        }
        __syncthreads();

        // phase b: z[8 pt][8 co] += sAgg x WdT
#pragma unroll 4
        for (int ci = 0; ci < CCH; ci++) {
            const ulonglong2* wp = (const ulonglong2*)(WdT + ci * 64 + cog * 8);
            ulonglong2 wA = wp[0];
            ulonglong2 wB = wp[1];
#pragma unroll
            for (int k = 0; k < 8; k++) {
                float av = sAgg[(ptg * 8 + k) * 66 + ci];
                uint64_t ad = pack2(av, av);
                fma2(zacc[k * 4 + 0], wA.x, ad);
                fma2(zacc[k * 4 + 1], wA.y, ad);
                fma2(zacc[k * 4 + 2], wB.x, ad);
                fma2(zacc[k * 4 + 3], wB.y, ad);
            }
        }
    }

    // epilogue: BN + residual + relu
#pragma unroll
    for (int k = 0; k < 8; k++) {
        int pt = ptg * 8 + k;
        if (pt >= TT2 * VV) break;
        int tl = pt / 25;
        int vv = pt - tl * 25;
        int base = nb + (t0 + tl) * VV + vv;
#pragma unroll
        for (int p = 0; p < 4; p++) {
            float2 zz = unpack2(zacc[k * 4 + p]);
            int c0 = cog * 8 + 2 * p;
            int c1 = c0 + 1;
            float val0 = ka[c0] * zz.x + kb[c0] + xs[pt * 68 + c0];
            float val1 = ka[c1] * zz.y + kb[c1] + xs[pt * 68 + c1];
            out[base + c0 * TV] = fmaxf(val0, 0.f);
            out[base + c1 * TV] = fmaxf(val1, 0.f);
        }
    }
}

// ---------------------------------------------------------------------------
// launch
// ---------------------------------------------------------------------------
extern "C" void kernel_launch(void* const* d_in, const int* in_sizes, int n_in,
                              void* d_out, int out_size) {
    const float* x    = (const float*)d_in[0];
    const float* wts  = (const float*)d_in[1];
    const float* A    = (const float*)d_in[2];
    const float* PA   = (const float*)d_in[3];
    const float* Wd   = (const float*)d_in[4];
    const float* bd   = (const float*)d_in[5];
    const float* WT1  = (const float*)d_in[6];
    const float* bT1  = (const float*)d_in[7];
    const float* WT2  = (const float*)d_in[8];
    const float* bT2  = (const float*)d_in[9];
    const float* bng  = (const float*)d_in[10];
    const float* bnb  = (const float*)d_in[11];
    const float* bnm  = (const float*)d_in[12];
    const float* bnv  = (const float*)d_in[13];
    float* out = (float*)d_out;

    const int conv_smem = CCH * 9 * 32 * 4;                        // 73728
    const int aggz_smem = (17000 + 4096 + 625 + 128 + 16896) * 4;  // 154980
    cudaFuncSetAttribute(k_conv, cudaFuncAttributeMaxDynamicSharedMemorySize, conv_smem);
    cudaFuncSetAttribute(k_aggz, cudaFuncAttributeMaxDynamicSharedMemorySize, aggz_smem);

    k_afull<<<1, 640>>>(A, PA);
    k_conv<<<dim3(6, NB, SS), 500, conv_smem>>>(x, WT1, bT1, WT2, bT2, wts);
    k_att<<<dim3(NB, SS), 640>>>();
    k_aggz<<<dim3(TT / TT2, NB), 256, aggz_smem>>>(x, Wd, bd, wts, bng, bnb, bnm, bnv, out);
}

// round 7
// speedup vs baseline: 1.1847x; 1.1365x over previous
#include <cuda_runtime.h>
#include <cuda_fp16.h>
#include <math.h>
#include <stdint.h>

// ---------------------------------------------------------------------------
// Problem constants
// ---------------------------------------------------------------------------
#define NB   64     // batch
#define CCH  64     // channels
#define TT   300    // time
#define VV   25     // vertices
#define SS   3      // subsets
#define IC   16     // inter channels
#define TV   (TT*VV)          // 7500
#define KROWS (IC*TT)         // 4800

// Scratch (device globals — no allocation allowed)
__device__ __half  g_t1h[SS * NB * IC * TV];
__device__ __half  g_t2h[SS * NB * IC * TV];
__device__ float   g_A1[SS * NB * VV * VV];
__device__ float   g_Afull[SS * VV * VV];
__device__ __half2 g_Whd[SS * 576 * 32];   // dup'd half2 weights [s][ci*9+dt][slot]

// ---------------------------------------------------------------------------
// Packed fp32x2 helpers (used in k_aggz)
// ---------------------------------------------------------------------------
__device__ __forceinline__ void fma2(uint64_t& d, uint64_t a, uint64_t b) {
    asm("fma.rn.f32x2 %0, %1, %2, %0;" : "+l"(d) : "l"(a), "l"(b));
}
__device__ __forceinline__ uint64_t pack2(float lo, float hi) {
    uint64_t r;
    asm("mov.b64 %0, {%1, %2};" : "=l"(r) : "f"(lo), "f"(hi));
    return r;
}
__device__ __forceinline__ float2 unpack2(uint64_t v) {
    float2 r;
    asm("mov.b64 {%0, %1}, %2;" : "=f"(r.x), "=f"(r.y) : "l"(v));
    return r;
}

// ---------------------------------------------------------------------------
// K0: A_full = A + PA + (8A^4 - 4A^2 - 4A + I)
// ---------------------------------------------------------------------------
__global__ void k_afull(const float* __restrict__ A, const float* __restrict__ PA) {
    for (int idx = threadIdx.x; idx < SS * VV * VV; idx += blockDim.x) {
        int r = idx % (VV * VV);
        int v1 = r / VV, v2 = r % VV;
        float a = A[idx];
        float a2 = a * a;
        float ch = 8.f * a2 * a2 - 4.f * a2 - 4.f * a + (v1 == v2 ? 1.f : 0.f);
        g_Afull[idx] = a + PA[idx] + ch;
    }
}

// ---------------------------------------------------------------------------
// K0b: pre-duplicate conv weights to half2(w,w).
//   slot = cv*16 + co;  index = (s*576 + ci*9+dt)*32 + slot
// ---------------------------------------------------------------------------
__global__ void k_wprep(const float* __restrict__ WT1, const float* __restrict__ WT2) {
    for (int idx = threadIdx.x + blockIdx.x * blockDim.x; idx < SS * 576 * 32;
         idx += blockDim.x * gridDim.x) {
        int slot = idx & 31;
        int kd   = (idx >> 5) % 576;
        int s    = idx / (576 * 32);
        int ci = kd / 9, dt = kd - 9 * (kd / 9);
        int cv = slot >> 4, co = slot & 15;
        float w = cv ? WT2[((s * IC + co) * CCH + ci) * 9 + dt]
                     : WT1[((s * IC + co) * CCH + ci) * 9 + dt];
        __half h = __float2half(w);
        g_Whd[idx] = __halves2half2(h, h);
    }
}

// ---------------------------------------------------------------------------
// K1 v4: slim_conv, HFMA2 inner (t-pair packed lanes), fp16 accumulate.
//   Thread = (cog 0..3, tg 0..4, v 0..24): 8 co-slots x 10 t (5 half2 pairs).
//   Inner (ci,dt): 2 LDS.128 (dup weights, broadcast) + 40 HFMA2.
// grid (6, N, S); block 500; smem 73728 B.
// ---------------------------------------------------------------------------
__global__ __launch_bounds__(500, 1)
void k_conv(const float* __restrict__ x,
            const float* __restrict__ bT1, const float* __restrict__ bT2,
            const float* __restrict__ weights) {
    const int s = blockIdx.z;
    const int n = blockIdx.y;
    extern __shared__ __half2 sw[];   // 576*32 half2 = 73728 B

    {
        const uint4* src = (const uint4*)(g_Whd + s * 576 * 32);
        uint4* dst = (uint4*)sw;
        for (int i = threadIdx.x; i < 576 * 32 / 4; i += 500) dst[i] = src[i];
    }
    __syncthreads();

    const int tid = threadIdx.x;
    const int cog = tid / 125;           // 0..3
    const int r   = tid - cog * 125;
    const int tg  = r / 25;              // 0..4
    const int v   = r - tg * 25;
    const int t0  = blockIdx.x * 50 + tg * 10;

    half2 hacc[40];                      // [slot j][tpair tp] = hacc[j*5+tp]
    const half2 hz = __float2half2_rn(0.f);
#pragma unroll
    for (int i = 0; i < 40; i++) hacc[i] = hz;

    const float* xb = x + n * CCH * TV + v;

    for (int ci = 0; ci < CCH; ci++) {
        const float* xp = xb + ci * TV;
        float xr[18];
#pragma unroll
        for (int k = 0; k < 18; k++) {
            int tt = t0 - 4 + k;
            xr[k] = (tt >= 0 && tt < TT) ? __ldg(xp + tt * VV) : 0.f;
        }
        half2 xe[9], xo[8];
#pragma unroll
        for (int j = 0; j < 9; j++) xe[j] = __floats2half2_rn(xr[2 * j], xr[2 * j + 1]);
#pragma unroll
        for (int j = 0; j < 8; j++) xo[j] = __floats2half2_rn(xr[2 * j + 1], xr[2 * j + 2]);

#pragma unroll
        for (int dt = 0; dt < 9; dt++) {
            const uint4* wp = (const uint4*)(sw + (ci * 9 + dt) * 32 + cog * 8);
            uint4 wa = wp[0];
            uint4 wb = wp[1];
            half2 w[8];
            *(uint4*)(w) = wa;
            *(uint4*)(w + 4) = wb;
            const half2* xv = (dt & 1) ? (xo + (dt >> 1)) : (xe + (dt >> 1));
#pragma unroll
            for (int j = 0; j < 8; j++) {
#pragma unroll
                for (int tp = 0; tp < 5; tp++) {
                    hacc[j * 5 + tp] = __hfma2(w[j], xv[tp], hacc[j * 5 + tp]);
                }
            }
        }
    }

    // epilogue: slim scale + bias, store fp16
    const int cv = cog >> 1;
    const int cb = (cog & 1) * 8;
    const float ws1 = __ldg(weights + 1), ws2 = __ldg(weights + 2);
    const float ws3 = __ldg(weights + 3), ws4 = __ldg(weights + 4);
    const float* bsrc = cv ? bT2 : bT1;
    __half* gout = cv ? g_t2h : g_t1h;
    const size_t obase = (size_t)(s * NB + n) * IC * TV + v;
#pragma unroll
    for (int j = 0; j < 8; j++) {
        int co = cb + j;
        // slim splits for out_c=16: 9, 11, 12, 14
        float sc = (co < 9) ? 1.f : (co < 11) ? ws1 : (co < 12) ? ws2 : (co < 14) ? ws3 : ws4;
        float b = __ldg(bsrc + s * IC + co);
        size_t oc = obase + (size_t)co * TV + (size_t)t0 * VV;
#pragma unroll
        for (int tp = 0; tp < 5; tp++) {
            float2 f = __half22float2(hacc[j * 5 + tp]);
            gout[oc + (2 * tp) * VV]     = __float2half(sc * (f.x + b));
            gout[oc + (2 * tp + 1) * VV] = __float2half(sc * (f.y + b));
        }
    }
}

// ---------------------------------------------------------------------------
// K2: attention logits + softmax(axis=-2 over v1) + A_full -> A1 (fp16 in)
// ---------------------------------------------------------------------------
__global__ __launch_bounds__(640, 2)
void k_att() {
    const int n = blockIdx.x;
    const int s = blockIdx.y;
    __shared__ float s1[64 * VV];
    __shared__ float s2[64 * VV];
    __shared__ float sl[VV * VV];

    const __half* t1b = g_t1h + (size_t)(s * NB + n) * IC * TV;
    const __half* t2b = g_t2h + (size_t)(s * NB + n) * IC * TV;

    const int tid = threadIdx.x;
    const int v1 = tid / 25;
    const int v2 = tid - v1 * 25;
    const bool act = tid < VV * VV;
    float acc = 0.f;

    for (int ch = 0; ch < KROWS / 64; ch++) {
        for (int idx = tid; idx < 64 * VV; idx += 640) {
            int row = idx / VV, vv = idx - row * VV;
            int cr = ch * 64 + row;
            int c = cr / TT, t = cr - c * TT;
            int off = c * TV + t * VV + vv;
            s1[idx] = __half2float(t1b[off]);
            s2[idx] = __half2float(t2b[off]);
        }
        __syncthreads();
        if (act) {
#pragma unroll 8
            for (int k = 0; k < 64; k++)
                acc += s1[k * VV + v1] * s2[k * VV + v2];
        }
        __syncthreads();
    }

    if (act) sl[tid] = acc * (1.0f / (float)KROWS);
    __syncthreads();

    if (tid < VV) {
        const int c2 = tid;
        float m = -1e30f;
#pragma unroll
        for (int r = 0; r < VV; r++) m = fmaxf(m, sl[r * VV + c2]);
        float sum = 0.f;
#pragma unroll
        for (int r = 0; r < VV; r++) sum += expf(sl[r * VV + c2] - m);
        float inv = 1.f / sum;
        const float* af = g_Afull + s * VV * VV;
        float* a1o = g_A1 + (size_t)(s * NB + n) * VV * VV;
#pragma unroll
        for (int r = 0; r < VV; r++)
            a1o[r * VV + c2] = af[r * VV + c2] + expf(sl[r * VV + c2] - m) * inv;
    }
}

// ---------------------------------------------------------------------------
// K3: agg + Wd fold + BN + residual + relu (R4 version — best known)
// grid: (30, N), block 256 (250 active, one (t,v2) each)
// ---------------------------------------------------------------------------
#define TT2 10
__global__ __launch_bounds__(256, 2)
void k_aggz(const float* __restrict__ x,
            const float* __restrict__ Wd, const float* __restrict__ bd,
            const float* __restrict__ weights,
            const float* __restrict__ bng, const float* __restrict__ bnb,
            const float* __restrict__ bnm, const float* __restrict__ bnv,
            float* __restrict__ out) {
    extern __shared__ float sm[];
    float* xs  = sm;              // 250*68 = 17000
    float* WdT = xs + 17000;      // 4096
    float* A1s = WdT + 4096;      // 625
    float* ka  = A1s + 625;       // 64
    float* kb  = ka + 64;         // 64

    const int n  = blockIdx.y;
    const int t0 = blockIdx.x * TT2;
    const int tid = threadIdx.x;
    const int nb = n * CCH * TV;

    for (int idx = tid; idx < CCH * TT2 * VV; idx += 256) {
        int ci = idx / (TT2 * VV);
        int tv = idx - ci * (TT2 * VV);
        xs[tv * 68 + ci] = x[nb + ci * TV + t0 * VV + tv];
    }
    if (tid < CCH) {
        int co = tid;
        float ws1 = weights[1], ws2 = weights[2], ws3 = weights[3], ws4 = weights[4];
        // slim splits for out_c=64: 38, 44, 51, 57
        float sc = (co < 38) ? 1.f : (co < 44) ? ws1 : (co < 51) ? ws2 : (co < 57) ? ws3 : ws4;
        float bdsum = bd[co] + bd[CCH + co] + bd[2 * CCH + co];
        float fa = bng[co] * rsqrtf(bnv[co] + 1e-5f);
        ka[co] = fa * sc;
        kb[co] = fa * sc * bdsum + bnb[co] - bnm[co] * fa;
    }

    uint64_t zacc[32];
    const uint64_t z2 = pack2(0.f, 0.f);
#pragma unroll
    for (int i = 0; i < 32; i++) zacc[i] = z2;

    const int tv = tid;
    const bool act = tid < TT2 * VV;
    const int tloc = tv / 25;
    const int v2 = tv - tloc * 25;

    for (int s = 0; s < SS; s++) {
        __syncthreads();
        for (int idx = tid; idx < CCH * CCH; idx += 256) {
            int ci = idx >> 6;
            int co = idx & 63;
            WdT[ci * 64 + co] = Wd[(s * CCH + co) * CCH + ci];
        }
        for (int idx = tid; idx < VV * VV; idx += 256)
            A1s[idx] = g_A1[(size_t)(s * NB + n) * VV * VV + idx];
        __syncthreads();

        if (act) {
#pragma unroll
            for (int cb = 0; cb < 64; cb += 16) {
                uint64_t ap[8];
#pragma unroll
                for (int i = 0; i < 8; i++) ap[i] = z2;
#pragma unroll
                for (int vv1 = 0; vv1 < VV; vv1++) {
                    float aw = A1s[vv1 * VV + v2];
                    uint64_t awp = pack2(aw, aw);
                    const ulonglong2* xp = (const ulonglong2*)(xs + (tloc * 25 + vv1) * 68 + cb);
#pragma unroll
                    for (int q = 0; q < 4; q++) {
                        ulonglong2 xv = xp[q];
                        fma2(ap[2*q],   xv.x, awp);
                        fma2(ap[2*q+1], xv.y, awp);
                    }
                }
#pragma unroll
                for (int i = 0; i < 8; i++) {
                    float2 af = unpack2(ap[i]);
                    uint64_t av0 = pack2(af.x, af.x);
                    uint64_t av1 = pack2(af.y, af.y);
                    const ulonglong2* w0 = (const ulonglong2*)(WdT + (cb + 2*i) * 64);
                    const ulonglong2* w1 = (const ulonglong2*)(WdT + (cb + 2*i + 1) * 64);
#pragma unroll
                    for (int q = 0; q < 16; q++) {
                        ulonglong2 wv0 = w0[q];
                        fma2(zacc[2*q],   wv0.x, av0);
                        fma2(zacc[2*q+1], wv0.y, av0);
                    }
#pragma unroll
                    for (int q = 0; q < 16; q++) {
                        ulonglong2 wv1 = w1[q];
                        fma2(zacc[2*q],   wv1.x, av1);
                        fma2(zacc[2*q+1], wv1.y, av1);
                    }
                }
            }
        }
    }

    if (act) {
        const float* xrow = xs + (tloc * 25 + v2) * 68;
        const int ob = nb + t0 * VV + tv;
#pragma unroll
        for (int cp = 0; cp < 32; cp++) {
            float2 zz = unpack2(zacc[cp]);
            int c0 = 2 * cp, c1 = 2 * cp + 1;
            float val0 = ka[c0] * zz.x + kb[c0] + xrow[c0];
            float val1 = ka[c1] * zz.y + kb[c1] + xrow[c1];
            out[ob + c0 * TV] = fmaxf(val0, 0.f);
            out[ob + c1 * TV] = fmaxf(val1, 0.f);
        }
    }
}

// ---------------------------------------------------------------------------
// launch
// ---------------------------------------------------------------------------
extern "C" void kernel_launch(void* const* d_in, const int* in_sizes, int n_in,
                              void* d_out, int out_size) {
    const float* x    = (const float*)d_in[0];
    const float* wts  = (const float*)d_in[1];
    const float* A    = (const float*)d_in[2];
    const float* PA   = (const float*)d_in[3];
    const float* Wd   = (const float*)d_in[4];
    const float* bd   = (const float*)d_in[5];
    const float* WT1  = (const float*)d_in[6];
    const float* bT1  = (const float*)d_in[7];
    const float* WT2  = (const float*)d_in[8];
    const float* bT2  = (const float*)d_in[9];
    const float* bng  = (const float*)d_in[10];
    const float* bnb  = (const float*)d_in[11];
    const float* bnm  = (const float*)d_in[12];
    const float* bnv  = (const float*)d_in[13];
    float* out = (float*)d_out;

    const int conv_smem = 576 * 32 * 4;                   // 73728 (half2)
    const int aggz_smem = (17000 + 4096 + 625 + 128) * 4; // 87396
    cudaFuncSetAttribute(k_conv, cudaFuncAttributeMaxDynamicSharedMemorySize, conv_smem);
    cudaFuncSetAttribute(k_aggz, cudaFuncAttributeMaxDynamicSharedMemorySize, aggz_smem);

    k_afull<<<1, 640>>>(A, PA);
    k_wprep<<<54, 1024>>>(WT1, WT2);
    k_conv<<<dim3(6, NB, SS), 500, conv_smem>>>(x, bT1, bT2, wts);
    k_att<<<dim3(NB, SS), 640>>>();
    k_aggz<<<dim3(TT / TT2, NB), 256, aggz_smem>>>(x, Wd, bd, wts, bng, bnb, bnm, bnv, out);
}

// round 8
// speedup vs baseline: 1.3285x; 1.1214x over previous
#include <cuda_runtime.h>
#include <cuda_fp16.h>
#include <math.h>
#include <stdint.h>

// ---------------------------------------------------------------------------
// Problem constants
// ---------------------------------------------------------------------------
#define NB   64     // batch
#define CCH  64     // channels
#define TT   300    // time
#define VV   25     // vertices
#define SS   3      // subsets
#define IC   16     // inter channels
#define TV   (TT*VV)          // 7500
#define KROWS (IC*TT)         // 4800
#define KS   3                // k-split for attention
#define KPB  (KROWS/KS)       // 1600 k-rows per attention block
#define ACH  160              // staged chunk (k-rows)

// Scratch (device globals — no allocation allowed)
__device__ __half  g_t1h[SS * NB * IC * TV];
__device__ __half  g_t2h[SS * NB * IC * TV];
__device__ float   g_A1[SS * NB * VV * VV];
__device__ float   g_Afull[SS * VV * VV];
__device__ __half2 g_Whd[SS * 576 * 32];     // dup'd half2 weights
__device__ float   g_plog[SS * NB * KS * 640]; // attention partial logits

// ---------------------------------------------------------------------------
// Packed fp32x2 helpers (used in k_aggz)
// ---------------------------------------------------------------------------
__device__ __forceinline__ void fma2(uint64_t& d, uint64_t a, uint64_t b) {
    asm("fma.rn.f32x2 %0, %1, %2, %0;" : "+l"(d) : "l"(a), "l"(b));
}
__device__ __forceinline__ uint64_t pack2(float lo, float hi) {
    uint64_t r;
    asm("mov.b64 %0, {%1, %2};" : "=l"(r) : "f"(lo), "f"(hi));
    return r;
}
__device__ __forceinline__ float2 unpack2(uint64_t v) {
    float2 r;
    asm("mov.b64 {%0, %1}, %2;" : "=f"(r.x), "=f"(r.y) : "l"(v));
    return r;
}

// ---------------------------------------------------------------------------
// K0: A_full = A + PA + (8A^4 - 4A^2 - 4A + I)
// ---------------------------------------------------------------------------
__global__ void k_afull(const float* __restrict__ A, const float* __restrict__ PA) {
    for (int idx = threadIdx.x; idx < SS * VV * VV; idx += blockDim.x) {
        int r = idx % (VV * VV);
        int v1 = r / VV, v2 = r % VV;
        float a = A[idx];
        float a2 = a * a;
        float ch = 8.f * a2 * a2 - 4.f * a2 - 4.f * a + (v1 == v2 ? 1.f : 0.f);
        g_Afull[idx] = a + PA[idx] + ch;
    }
}

// ---------------------------------------------------------------------------
// K0b: pre-duplicate conv weights to half2(w,w)
// ---------------------------------------------------------------------------
__global__ void k_wprep(const float* __restrict__ WT1, const float* __restrict__ WT2) {
    for (int idx = threadIdx.x + blockIdx.x * blockDim.x; idx < SS * 576 * 32;
         idx += blockDim.x * gridDim.x) {
        int slot = idx & 31;
        int kd   = (idx >> 5) % 576;
        int s    = idx / (576 * 32);
        int ci = kd / 9, dt = kd - 9 * (kd / 9);
        int cv = slot >> 4, co = slot & 15;
        float w = cv ? WT2[((s * IC + co) * CCH + ci) * 9 + dt]
                     : WT1[((s * IC + co) * CCH + ci) * 9 + dt];
        __half h = __float2half(w);
        g_Whd[idx] = __halves2half2(h, h);
    }
}

// ---------------------------------------------------------------------------
// K1 v5: slim_conv HFMA2, with interior fast path (no bounds predication).
// grid (6, N, S); block 500; smem 73728 B.
// ---------------------------------------------------------------------------
__global__ __launch_bounds__(500, 1)
void k_conv(const float* __restrict__ x,
            const float* __restrict__ bT1, const float* __restrict__ bT2,
            const float* __restrict__ weights) {
    const int s = blockIdx.z;
    const int n = blockIdx.y;
    extern __shared__ __half2 sw[];   // 576*32 half2 = 73728 B

    {
        const uint4* src = (const uint4*)(g_Whd + s * 576 * 32);
        uint4* dst = (uint4*)sw;
        for (int i = threadIdx.x; i < 576 * 32 / 4; i += 500) dst[i] = src[i];
    }
    __syncthreads();

    const int tid = threadIdx.x;
    const int cog = tid / 125;           // 0..3
    const int r   = tid - cog * 125;
    const int tg  = r / 25;              // 0..4
    const int v   = r - tg * 25;
    const int t0  = blockIdx.x * 50 + tg * 10;
    const bool interior = (t0 >= 4) && (t0 + 13 < TT);

    half2 hacc[40];                      // [slot j][tpair tp] = hacc[j*5+tp]
    const half2 hz = __float2half2_rn(0.f);
#pragma unroll
    for (int i = 0; i < 40; i++) hacc[i] = hz;

    const float* xb = x + n * CCH * TV + v;

    for (int ci = 0; ci < CCH; ci++) {
        const float* xp = xb + ci * TV + (t0 - 4) * VV;
        float xr[18];
        if (interior) {
#pragma unroll
            for (int k = 0; k < 18; k++) xr[k] = __ldg(xp + k * VV);
        } else {
#pragma unroll
            for (int k = 0; k < 18; k++) {
                int tt = t0 - 4 + k;
                xr[k] = (tt >= 0 && tt < TT) ? __ldg(xp + k * VV) : 0.f;
            }
        }
        half2 xe[9], xo[8];
#pragma unroll
        for (int j = 0; j < 9; j++) xe[j] = __floats2half2_rn(xr[2 * j], xr[2 * j + 1]);
#pragma unroll
        for (int j = 0; j < 8; j++) xo[j] = __floats2half2_rn(xr[2 * j + 1], xr[2 * j + 2]);

#pragma unroll
        for (int dt = 0; dt < 9; dt++) {
            const uint4* wp = (const uint4*)(sw + (ci * 9 + dt) * 32 + cog * 8);
            uint4 wa = wp[0];
            uint4 wb = wp[1];
            half2 w[8];
            *(uint4*)(w) = wa;
            *(uint4*)(w + 4) = wb;
            const half2* xv = (dt & 1) ? (xo + (dt >> 1)) : (xe + (dt >> 1));
#pragma unroll
            for (int j = 0; j < 8; j++) {
#pragma unroll
                for (int tp = 0; tp < 5; tp++) {
                    hacc[j * 5 + tp] = __hfma2(w[j], xv[tp], hacc[j * 5 + tp]);
                }
            }
        }
    }

    // epilogue: slim scale + bias, store fp16
    const int cv = cog >> 1;
    const int cb = (cog & 1) * 8;
    const float ws1 = __ldg(weights + 1), ws2 = __ldg(weights + 2);
    const float ws3 = __ldg(weights + 3), ws4 = __ldg(weights + 4);
    const float* bsrc = cv ? bT2 : bT1;
    __half* gout = cv ? g_t2h : g_t1h;
    const size_t obase = (size_t)(s * NB + n) * IC * TV + v;
#pragma unroll
    for (int j = 0; j < 8; j++) {
        int co = cb + j;
        // slim splits for out_c=16: 9, 11, 12, 14
        float sc = (co < 9) ? 1.f : (co < 11) ? ws1 : (co < 12) ? ws2 : (co < 14) ? ws3 : ws4;
        float b = __ldg(bsrc + s * IC + co);
        size_t oc = obase + (size_t)co * TV + (size_t)t0 * VV;
#pragma unroll
        for (int tp = 0; tp < 5; tp++) {
            float2 f = __half22float2(hacc[j * 5 + tp]);
            gout[oc + (2 * tp) * VV]     = __float2half(sc * (f.x + b));
            gout[oc + (2 * tp + 1) * VV] = __float2half(sc * (f.y + b));
        }
    }
}

// ---------------------------------------------------------------------------
// K2a: attention partial logits.  grid (N, S, KS), block 640.
//   Stage transposed fp16 [v][k] chunks (stride 166 halfs = 83 half2,
//   conflict-free), HFMA2 dot with fp32 spill every 16 half2.
// ---------------------------------------------------------------------------
__global__ __launch_bounds__(640, 2)
void k_att2() {
    const int n  = blockIdx.x;
    const int s  = blockIdx.y;
    const int kc = blockIdx.z;
    __shared__ __half s1t[25 * 166];
    __shared__ __half s2t[25 * 166];

    const __half* t1b = g_t1h + (size_t)(s * NB + n) * IC * TV;
    const __half* t2b = g_t2h + (size_t)(s * NB + n) * IC * TV;

    const int tid = threadIdx.x;
    const int v1 = tid / 25;
    const int v2 = tid - v1 * 25;
    const bool act = tid < VV * VV;
    float acc = 0.f;

    for (int ch = 0; ch < KPB / ACH; ch++) {
        const int kbase = kc * KPB + ch * ACH;
        for (int idx = tid; idx < ACH * VV; idx += 640) {
            int kk = idx / VV;
            int v  = idx - kk * VV;
            int k  = kbase + kk;
            int c  = k / TT;
            int t  = k - c * TT;
            int off = c * TV + t * VV + v;
            s1t[v * 166 + kk] = t1b[off];
            s2t[v * 166 + kk] = t2b[off];
        }
        __syncthreads();
        if (act) {
            const half2* p1 = (const half2*)s1t + v1 * 83;
            const half2* p2 = (const half2*)s2t + v2 * 83;
#pragma unroll
            for (int g = 0; g < 5; g++) {
                half2 ph = __float2half2_rn(0.f);
#pragma unroll
                for (int j = 0; j < 16; j++)
                    ph = __hfma2(p1[g * 16 + j], p2[g * 16 + j], ph);
                float2 f = __half22float2(ph);
                acc += f.x + f.y;
            }
        }
        __syncthreads();
    }

    g_plog[((size_t)(s * NB + n) * KS + kc) * 640 + tid] = acc;
}

// ---------------------------------------------------------------------------
// K2b: reduce partials + softmax(axis=-2 over v1) + A_full -> A1
// grid (N, S), block 640.
// ---------------------------------------------------------------------------
__global__ __launch_bounds__(640, 2)
void k_soft() {
    const int n = blockIdx.x;
    const int s = blockIdx.y;
    __shared__ float sl[VV * VV];
    const int tid = threadIdx.x;

    if (tid < VV * VV) {
        const float* pb = g_plog + (size_t)(s * NB + n) * KS * 640 + tid;
        float a = pb[0] + pb[640] + pb[1280];
        sl[tid] = a * (1.0f / (float)KROWS);
    }
    __syncthreads();

    if (tid < VV) {
        const int c2 = tid;
        float m = -1e30f;
#pragma unroll
        for (int r = 0; r < VV; r++) m = fmaxf(m, sl[r * VV + c2]);
        float sum = 0.f;
#pragma unroll
        for (int r = 0; r < VV; r++) sum += expf(sl[r * VV + c2] - m);
        float inv = 1.f / sum;
        const float* af = g_Afull + s * VV * VV;
        float* a1o = g_A1 + (size_t)(s * NB + n) * VV * VV;
#pragma unroll
        for (int r = 0; r < VV; r++)
            a1o[r * VV + c2] = af[r * VV + c2] + expf(sl[r * VV + c2] - m) * inv;
    }
}

// ---------------------------------------------------------------------------
// K3: agg + Wd fold + BN + residual + relu (R4 version — best known)
// ---------------------------------------------------------------------------
#define TT2 10
__global__ __launch_bounds__(256, 2)
void k_aggz(const float* __restrict__ x,
            const float* __restrict__ Wd, const float* __restrict__ bd,
            const float* __restrict__ weights,
            const float* __restrict__ bng, const float* __restrict__ bnb,
            const float* __restrict__ bnm, const float* __restrict__ bnv,
            float* __restrict__ out) {
    extern __shared__ float sm[];
    float* xs  = sm;              // 250*68 = 17000
    float* WdT = xs + 17000;      // 4096
    float* A1s = WdT + 4096;      // 625
    float* ka  = A1s + 625;       // 64
    float* kb  = ka + 64;         // 64

    const int n  = blockIdx.y;
    const int t0 = blockIdx.x * TT2;
    const int tid = threadIdx.x;
    const int nb = n * CCH * TV;

    for (int idx = tid; idx < CCH * TT2 * VV; idx += 256) {
        int ci = idx / (TT2 * VV);
        int tv = idx - ci * (TT2 * VV);
        xs[tv * 68 + ci] = x[nb + ci * TV + t0 * VV + tv];
    }
    if (tid < CCH) {
        int co = tid;
        float ws1 = weights[1], ws2 = weights[2], ws3 = weights[3], ws4 = weights[4];
        // slim splits for out_c=64: 38, 44, 51, 57
        float sc = (co < 38) ? 1.f : (co < 44) ? ws1 : (co < 51) ? ws2 : (co < 57) ? ws3 : ws4;
        float bdsum = bd[co] + bd[CCH + co] + bd[2 * CCH + co];
        float fa = bng[co] * rsqrtf(bnv[co] + 1e-5f);
        ka[co] = fa * sc;
        kb[co] = fa * sc * bdsum + bnb[co] - bnm[co] * fa;
    }

    uint64_t zacc[32];
    const uint64_t z2 = pack2(0.f, 0.f);
#pragma unroll
    for (int i = 0; i < 32; i++) zacc[i] = z2;

    const int tv = tid;
    const bool act = tid < TT2 * VV;
    const int tloc = tv / 25;
    const int v2 = tv - tloc * 25;

    for (int s = 0; s < SS; s++) {
        __syncthreads();
        for (int idx = tid; idx < CCH * CCH; idx += 256) {
            int ci = idx >> 6;
            int co = idx & 63;
            WdT[ci * 64 + co] = Wd[(s * CCH + co) * CCH + ci];
        }
        for (int idx = tid; idx < VV * VV; idx += 256)
            A1s[idx] = g_A1[(size_t)(s * NB + n) * VV * VV + idx];
        __syncthreads();

        if (act) {
#pragma unroll
            for (int cb = 0; cb < 64; cb += 16) {
                uint64_t ap[8];
#pragma unroll
                for (int i = 0; i < 8; i++) ap[i] = z2;
#pragma unroll
                for (int vv1 = 0; vv1 < VV; vv1++) {
                    float aw = A1s[vv1 * VV + v2];
                    uint64_t awp = pack2(aw, aw);
                    const ulonglong2* xp = (const ulonglong2*)(xs + (tloc * 25 + vv1) * 68 + cb);
#pragma unroll
                    for (int q = 0; q < 4; q++) {
                        ulonglong2 xv = xp[q];
                        fma2(ap[2*q],   xv.x, awp);
                        fma2(ap[2*q+1], xv.y, awp);
                    }
                }
#pragma unroll
                for (int i = 0; i < 8; i++) {
                    float2 af = unpack2(ap[i]);
                    uint64_t av0 = pack2(af.x, af.x);
                    uint64_t av1 = pack2(af.y, af.y);
                    const ulonglong2* w0 = (const ulonglong2*)(WdT + (cb + 2*i) * 64);
                    const ulonglong2* w1 = (const ulonglong2*)(WdT + (cb + 2*i + 1) * 64);
#pragma unroll
                    for (int q = 0; q < 16; q++) {
                        ulonglong2 wv0 = w0[q];
                        fma2(zacc[2*q],   wv0.x, av0);
                        fma2(zacc[2*q+1], wv0.y, av0);
                    }
#pragma unroll
                    for (int q = 0; q < 16; q++) {
                        ulonglong2 wv1 = w1[q];
                        fma2(zacc[2*q],   wv1.x, av1);
                        fma2(zacc[2*q+1], wv1.y, av1);
                    }
                }
            }
        }
    }

    if (act) {
        const float* xrow = xs + (tloc * 25 + v2) * 68;
        const int ob = nb + t0 * VV + tv;
#pragma unroll
        for (int cp = 0; cp < 32; cp++) {
            float2 zz = unpack2(zacc[cp]);
            int c0 = 2 * cp, c1 = 2 * cp + 1;
            float val0 = ka[c0] * zz.x + kb[c0] + xrow[c0];
            float val1 = ka[c1] * zz.y + kb[c1] + xrow[c1];
            out[ob + c0 * TV] = fmaxf(val0, 0.f);
            out[ob + c1 * TV] = fmaxf(val1, 0.f);
        }
    }
}

// ---------------------------------------------------------------------------
// launch
// ---------------------------------------------------------------------------
extern "C" void kernel_launch(void* const* d_in, const int* in_sizes, int n_in,
                              void* d_out, int out_size) {
    const float* x    = (const float*)d_in[0];
    const float* wts  = (const float*)d_in[1];
    const float* A    = (const float*)d_in[2];
    const float* PA   = (const float*)d_in[3];
    const float* Wd   = (const float*)d_in[4];
    const float* bd   = (const float*)d_in[5];
    const float* WT1  = (const float*)d_in[6];
    const float* bT1  = (const float*)d_in[7];
    const float* WT2  = (const float*)d_in[8];
    const float* bT2  = (const float*)d_in[9];
    const float* bng  = (const float*)d_in[10];
    const float* bnb  = (const float*)d_in[11];
    const float* bnm  = (const float*)d_in[12];
    const float* bnv  = (const float*)d_in[13];
    float* out = (float*)d_out;

    const int conv_smem = 576 * 32 * 4;                   // 73728 (half2)
    const int aggz_smem = (17000 + 4096 + 625 + 128) * 4; // 87396
    cudaFuncSetAttribute(k_conv, cudaFuncAttributeMaxDynamicSharedMemorySize, conv_smem);
    cudaFuncSetAttribute(k_aggz, cudaFuncAttributeMaxDynamicSharedMemorySize, aggz_smem);

    k_afull<<<1, 640>>>(A, PA);
    k_wprep<<<54, 1024>>>(WT1, WT2);
    k_conv<<<dim3(6, NB, SS), 500, conv_smem>>>(x, bT1, bT2, wts);
    k_att2<<<dim3(NB, SS, KS), 640>>>();
    k_soft<<<dim3(NB, SS), 640>>>();
    k_aggz<<<dim3(TT / TT2, NB), 256, aggz_smem>>>(x, Wd, bd, wts, bng, bnb, bnm, bnv, out);
}